// round 1
// baseline (speedup 1.0000x reference)
#include <cuda_runtime.h>
#include <cstdint>

// Problem constants (fixed by the dataset)
#define NNODES 20000
#define NC 32
#define ND 128
#define BN 8                 // nodes per CTA
#define MROWS (BN * NC)      // 256 GEMM rows per CTA
#define NTHREADS 512
#define PAD 132              // padded row length (floats) for conflict-free smem

// Smem layout (in floats)
#define OFF_U     0
#define OFF_W1    (OFF_U + MROWS * PAD)          // 33792
#define OFF_MEAN  (OFF_W1 + ND * PAD)            // +16896 = 50688
#define OFF_Z2    (OFF_MEAN + BN * ND)           // +1024
#define OFF_Z3    (OFF_Z2 + BN * ND)             // +1024
#define OFF_B1    (OFF_Z3 + BN * ND)             // +1024
#define OFF_MASK  (OFF_B1 + ND)                  // +128
#define OFF_COL   (OFF_MASK + MROWS)             // +256 (ints)
#define OFF_NORM  (OFF_COL + BN)                 // +8
#define SMEM_FLOATS (OFF_NORM + BN)              // 54160 floats
#define SMEM_BYTES  (SMEM_FLOATS * 4)            // 216640 bytes

__device__ __forceinline__ uint32_t f2tf32(float x) {
    uint32_t r;
    asm("cvt.rna.tf32.f32 %0, %1;" : "=r"(r) : "f"(x));
    return r;
}

__device__ __forceinline__ void mma_tf32(float* d, const uint32_t* a,
                                         const uint32_t* b, const float* c) {
    asm volatile(
        "mma.sync.aligned.m16n8k8.row.col.f32.tf32.tf32.f32 "
        "{%0,%1,%2,%3}, {%4,%5,%6,%7}, {%8,%9}, {%10,%11,%12,%13};\n"
        : "=f"(d[0]), "=f"(d[1]), "=f"(d[2]), "=f"(d[3])
        : "r"(a[0]), "r"(a[1]), "r"(a[2]), "r"(a[3]),
          "r"(b[0]), "r"(b[1]),
          "f"(c[0]), "f"(c[1]), "f"(c[2]), "f"(c[3]));
}

__global__ void __launch_bounds__(NTHREADS, 1)
utou_fused_kernel(const float* __restrict__ u,
                  const float* __restrict__ mask,
                  const float* __restrict__ normalizer,
                  const int*   __restrict__ coloring,
                  const float* __restrict__ W1,
                  const float* __restrict__ b1,
                  const float* __restrict__ W2,
                  const float* __restrict__ W3,
                  float* __restrict__ out) {
    extern __shared__ float sm[];
    float* sU    = sm + OFF_U;
    float* sW1   = sm + OFF_W1;
    float* smean = sm + OFF_MEAN;
    float* sZ2   = sm + OFF_Z2;
    float* sZ3   = sm + OFF_Z3;
    float* sB1   = sm + OFF_B1;
    float* sMask = sm + OFF_MASK;
    int*   sCol  = (int*)(sm + OFF_COL);
    float* sNorm = sm + OFF_NORM;

    const int t = threadIdx.x;
    const int nodeBase = blockIdx.x * BN;
    const long long ubase = (long long)nodeBase * NC * ND;

    // ---- Stage u tile: 32768 floats (8192 float4), padded rows ----
    {
        const float4* ug = (const float4*)(u + ubase);
#pragma unroll
        for (int i = 0; i < 16; i++) {
            int idx = t + i * NTHREADS;        // 0..8191
            int row = idx >> 5;                // 32 float4 per 128-float row
            int c4  = idx & 31;
            float4 v = ug[idx];
            *(float4*)(sU + row * PAD + c4 * 4) = v;
        }
    }
    // ---- Stage W1 (tf32-rounded): 16384 floats (4096 float4) ----
    {
        const float4* wg = (const float4*)W1;
#pragma unroll
        for (int i = 0; i < 8; i++) {
            int idx = t + i * NTHREADS;        // 0..4095
            int row = idx >> 5;
            int c4  = idx & 31;
            float4 v = wg[idx];
            v.x = __uint_as_float(f2tf32(v.x));
            v.y = __uint_as_float(f2tf32(v.y));
            v.z = __uint_as_float(f2tf32(v.z));
            v.w = __uint_as_float(f2tf32(v.w));
            *(float4*)(sW1 + row * PAD + c4 * 4) = v;
        }
    }
    // ---- Stage small vectors ----
    if (t < ND) sB1[t] = b1[t];
    else if (t >= 128 && t < 128 + MROWS) sMask[t - 128] = mask[(long long)nodeBase * NC + (t - 128)];
    else if (t >= 384 && t < 384 + BN) sCol[t - 384] = coloring[nodeBase + (t - 384)];
    else if (t >= 392 && t < 392 + BN) sNorm[t - 392] = normalizer[nodeBase + (t - 392)];
    __syncthreads();

    // ---- mean2[i][d] = sum_c u[i,c,d] / normalizer ----
    {
        int d0 = t & 127;
        int i0 = t >> 7;   // 0..3
#pragma unroll
        for (int rep = 0; rep < 2; rep++) {
            int i = i0 + rep * 4;
            const float* base = sU + (i * NC) * PAD + d0;
            float s = 0.f;
#pragma unroll
            for (int c = 0; c < NC; c++) s += base[c * PAD];
            smean[i * ND + d0] = s / sNorm[i];
        }
    }
    __syncthreads();

    // ---- z2[i][e] = 0.1 * mean2[i] . W2[e,:]   z3f[i][e] = 0.1 * mean2[i] . W3[e,:] ----
    // 512 tasks: (mat, e, khalf). Adjacent lanes (t^1) share (mat,e), split K.
    {
        int khalf  = t & 1;
        int e      = (t >> 1) & 127;
        int matsel = t >> 8;                  // 0 -> W2, 1 -> W3
        const float* W = matsel ? W3 : W2;
        const float* wrow = W + e * ND + khalf * 64;
        const float* mh = smean + khalf * 64;
        float acc[BN];
#pragma unroll
        for (int i = 0; i < BN; i++) acc[i] = 0.f;
#pragma unroll 4
        for (int k = 0; k < 64; k++) {
            float w = wrow[k];
#pragma unroll
            for (int i = 0; i < BN; i++) acc[i] += mh[i * ND + k] * w;
        }
        float* dst = matsel ? sZ3 : sZ2;
#pragma unroll
        for (int i = 0; i < BN; i++) {
            float v = acc[i] + __shfl_xor_sync(0xffffffffu, acc[i], 1);
            if (khalf == 0) dst[i * ND + e] = 0.1f * v;
        }
    }
    __syncthreads();   // z results visible before epilogue; smem stable for GEMM

    // ---- Main GEMM: [256 x 128] = sU @ sW1^T via mma.sync tf32 ----
    const int wid  = t >> 5;
    const int lane = t & 31;
    const int warpM = wid >> 1;   // 0..7  (== node index within block)
    const int warpE = wid & 1;    // 0..1
    const int g  = lane >> 2;     // 0..7
    const int tg = lane & 3;      // 0..3

    float acc[2][8][4];
#pragma unroll
    for (int mt = 0; mt < 2; mt++)
#pragma unroll
        for (int nt = 0; nt < 8; nt++)
#pragma unroll
            for (int r = 0; r < 4; r++) acc[mt][nt][r] = 0.f;

    const float* Abase = sU  + (warpM * 32) * PAD + g * PAD + tg;
    const float* Bbase = sW1 + (warpE * 64) * PAD + g * PAD + tg;

#pragma unroll 4
    for (int ks = 0; ks < 16; ks++) {
        const int kc = ks * 8;
        uint32_t a[2][4];
#pragma unroll
        for (int mt = 0; mt < 2; mt++) {
            const float* ar = Abase + mt * 16 * PAD + kc;
            a[mt][0] = f2tf32(ar[0]);
            a[mt][1] = f2tf32(ar[8 * PAD]);
            a[mt][2] = f2tf32(ar[4]);
            a[mt][3] = f2tf32(ar[8 * PAD + 4]);
        }
#pragma unroll
        for (int nt = 0; nt < 8; nt++) {
            const float* br = Bbase + nt * 8 * PAD + kc;
            uint32_t b[2];
            b[0] = __float_as_uint(br[0]);
            b[1] = __float_as_uint(br[4]);
            mma_tf32(acc[0][nt], a[0], b, acc[0][nt]);
            mma_tf32(acc[1][nt], a[1], b, acc[1][nt]);
        }
    }

    // ---- Epilogue: + b1 + residual u + 0.1*mask*z3 + (c==color)*z2, write out ----
    float* outg = out + ubase;
    const int inode = warpM;                 // each warp owns one node
    const int mycol = sCol[inode];
#pragma unroll
    for (int mt = 0; mt < 2; mt++) {
#pragma unroll
        for (int half = 0; half < 2; half++) {
            const int m  = warpM * 32 + mt * 16 + half * 8 + g;
            const int cc = m & 31;
            const float zm = sMask[m];
            const bool hit = (cc == mycol);
#pragma unroll
            for (int nt = 0; nt < 8; nt++) {
                const int e = warpE * 64 + nt * 8 + tg * 2;
                float v0 = acc[mt][nt][half * 2 + 0];
                float v1 = acc[mt][nt][half * 2 + 1];
                const float* ur = sU + m * PAD + e;
                v0 += sB1[e]     + ur[0] + zm * sZ3[inode * ND + e];
                v1 += sB1[e + 1] + ur[1] + zm * sZ3[inode * ND + e + 1];
                if (hit) {
                    v0 += sZ2[inode * ND + e];
                    v1 += sZ2[inode * ND + e + 1];
                }
                *(float2*)(outg + (long long)m * ND + e) = make_float2(v0, v1);
            }
        }
    }
}

extern "C" void kernel_launch(void* const* d_in, const int* in_sizes, int n_in,
                              void* d_out, int out_size) {
    const float* u    = (const float*)d_in[0];
    const float* mask = (const float*)d_in[1];
    const float* norm = (const float*)d_in[2];
    const int*   col  = (const int*)d_in[3];
    const float* W1   = (const float*)d_in[4];
    const float* b1   = (const float*)d_in[5];
    const float* W2   = (const float*)d_in[6];
    const float* W3   = (const float*)d_in[7];
    float* out = (float*)d_out;

    cudaFuncSetAttribute(utou_fused_kernel,
                         cudaFuncAttributeMaxDynamicSharedMemorySize, SMEM_BYTES);

    const int grid = NNODES / BN;   // 2500
    utou_fused_kernel<<<grid, NTHREADS, SMEM_BYTES>>>(u, mask, norm, col,
                                                      W1, b1, W2, W3, out);
    (void)in_sizes; (void)n_in; (void)out_size;
}

// round 2
// speedup vs baseline: 2.3671x; 2.3671x over previous
#include <cuda_runtime.h>
#include <cstdint>

#define NNODES 20000
#define NC 32
#define ND 128
#define PAD 132   // padded smem row (floats): bank = 4g+tg, conflict-free frags

// ---- device scratch (allowed: __device__ globals, no runtime alloc) ----
__device__ float4 g_W1f[4096];        // paired-permuted tf32(W1 + I)      (64 KB)
__device__ float4 g_W23f[8192];       // paired-permuted tf32([W2;W3])     (128 KB)
__device__ float  g_z2[NNODES * ND];  // 0.1 * mean @ W2^T                 (10.2 MB)
__device__ float  g_z3[NNODES * ND];  // 0.1 * mean @ W3^T                 (10.2 MB)

__device__ __forceinline__ float tfr(float x) {
    uint32_t r;
    asm("cvt.rna.tf32.f32 %0, %1;" : "=r"(r) : "f"(x));
    return __uint_as_float(r);
}

__device__ __forceinline__ void mma_tf32(float* d, const uint32_t* a,
                                         uint32_t b0, uint32_t b1) {
    asm volatile(
        "mma.sync.aligned.m16n8k8.row.col.f32.tf32.tf32.f32 "
        "{%0,%1,%2,%3}, {%4,%5,%6,%7}, {%8,%9}, {%0,%1,%2,%3};\n"
        : "+f"(d[0]), "+f"(d[1]), "+f"(d[2]), "+f"(d[3])
        : "r"(a[0]), "r"(a[1]), "r"(a[2]), "r"(a[3]), "r"(b0), "r"(b1));
}

// ============================================================================
// Kernel 0: build permuted tf32 weight buffers.
// Fragment-friendly layout: for a warp, the 32 lanes' (b0,b1) pairs for one
// (n-tile-pair, ks) are contiguous 512B -> one coalesced LDG.128 per 2 n-tiles.
// ============================================================================
__global__ void prep_kernel(const float* __restrict__ W1,
                            const float* __restrict__ W2,
                            const float* __restrict__ W3) {
    int t0 = blockIdx.x * blockDim.x + threadIdx.x;
    int stride = gridDim.x * blockDim.x;
    // g_W1f[i], i = wE*2048 + ntp*512 + ks*32 + g*4 + tg
    for (int i = t0; i < 4096; i += stride) {
        int tg = i & 3, g = (i >> 2) & 7, ks = (i >> 5) & 15;
        int ntp = (i >> 9) & 3, wE = (i >> 11) & 1;
        int e0 = wE * 64 + ntp * 16 + g, e1 = e0 + 8;
        int k0 = ks * 8 + tg, k1 = k0 + 4;
        g_W1f[i] = make_float4(
            tfr(W1[e0 * ND + k0] + (e0 == k0 ? 1.f : 0.f)),
            tfr(W1[e0 * ND + k1] + (e0 == k1 ? 1.f : 0.f)),
            tfr(W1[e1 * ND + k0] + (e1 == k0 ? 1.f : 0.f)),
            tfr(W1[e1 * ND + k1] + (e1 == k1 ? 1.f : 0.f)));
    }
    // g_W23f[i], i = w*1024 + ntp*512 + ks*32 + g*4 + tg ; rows e: [W2 | W3]
    for (int i = t0; i < 8192; i += stride) {
        int tg = i & 3, g = (i >> 2) & 7, ks = (i >> 5) & 15;
        int ntp = (i >> 9) & 1, w = (i >> 10) & 7;
        int e0 = w * 32 + ntp * 16 + g, e1 = e0 + 8;
        int k0 = ks * 8 + tg, k1 = k0 + 4;
        const float* r0 = (e0 < 128) ? (W2 + e0 * ND) : (W3 + (e0 - 128) * ND);
        const float* r1 = (e1 < 128) ? (W2 + e1 * ND) : (W3 + (e1 - 128) * ND);
        g_W23f[i] = make_float4(tfr(r0[k0]), tfr(r0[k1]), tfr(r1[k0]), tfr(r1[k1]));
    }
}

// ============================================================================
// Kernel 1: mean over colors (DRAM-bound stream) + z2/z3 via tiny tensor GEMM.
// BN=8 nodes per CTA, 256 threads.
// ============================================================================
__global__ void __launch_bounds__(256)
mean_z_kernel(const float* __restrict__ u, const float* __restrict__ normalizer) {
    __shared__ float smean[8 * PAD];
    const int t = threadIdx.x;
    const int nodeBase = blockIdx.x * 8;

    // ---- mean: thread (i = node-in-block, d4) streams 32 colors, coalesced ----
    {
        int i = t >> 5, d4 = t & 31;
        const float4* up = (const float4*)u + (nodeBase + i) * (NC * 32) + d4;
        float4 s = make_float4(0.f, 0.f, 0.f, 0.f);
#pragma unroll
        for (int c = 0; c < NC; c++) {
            float4 v = up[c * 32];
            s.x += v.x; s.y += v.y; s.z += v.z; s.w += v.w;
        }
        float inv = 1.f / normalizer[nodeBase + i];
        s.x = tfr(s.x * inv); s.y = tfr(s.y * inv);
        s.z = tfr(s.z * inv); s.w = tfr(s.w * inv);
        *(float4*)(smean + i * PAD + d4 * 4) = s;
    }
    __syncthreads();

    // ---- z = mean(8x128) @ W23^T (256x128) with M-padded m16n8k8 MMAs ----
    const int wid = t >> 5, lane = t & 31;
    const int g = lane >> 2, tg = lane & 3;
    float acc[4][4];
#pragma unroll
    for (int n = 0; n < 4; n++)
#pragma unroll
        for (int r = 0; r < 4; r++) acc[n][r] = 0.f;

    const float4* Bp = g_W23f + wid * 1024 + g * 4 + tg;
    const float* Ab = smean + g * PAD + tg;
#pragma unroll
    for (int ks = 0; ks < 16; ks++) {
        const int kc = ks * 8;
        uint32_t a[4];
        a[0] = __float_as_uint(Ab[kc]);
        a[1] = 0u;                        // rows 8..15 are padding
        a[2] = __float_as_uint(Ab[kc + 4]);
        a[3] = 0u;
#pragma unroll
        for (int ntp = 0; ntp < 2; ntp++) {
            float4 bb = Bp[ntp * 512 + ks * 32];
            mma_tf32(acc[2 * ntp + 0], a, __float_as_uint(bb.x), __float_as_uint(bb.y));
            mma_tf32(acc[2 * ntp + 1], a, __float_as_uint(bb.z), __float_as_uint(bb.w));
        }
    }

    // ---- scatter z (lane (g,tg) owns node g, cols e=wid*32+nt*8+tg*2) ----
    const int node = nodeBase + g;
#pragma unroll
    for (int nt = 0; nt < 4; nt++) {
        int e = wid * 32 + nt * 8 + tg * 2;
        float2 v = make_float2(0.1f * acc[nt][0], 0.1f * acc[nt][1]);
        if (e < 128) *(float2*)(g_z2 + node * ND + e) = v;
        else         *(float2*)(g_z3 + node * ND + (e - 128)) = v;
    }
}

// ============================================================================
// Kernel 2: out = u @ tf32(W1+I)^T + b1 + mask*z3 + (c==color)*z2
// BN=4 nodes (128 rows) per CTA, 256 threads = 4 warpM x 2 warpE,
// 2 CTAs/SM. A staged (tf32) in smem; B frags = 1 coalesced LDG.128 / 2 tiles.
// ============================================================================
__global__ void __launch_bounds__(256, 2)
main_gemm_kernel(const float* __restrict__ u,
                 const float* __restrict__ mask,
                 const int* __restrict__ coloring,
                 const float* __restrict__ b1,
                 float* __restrict__ out) {
    extern __shared__ float sU[];   // 128 x PAD floats = 67584 B
    const int t = threadIdx.x;
    const int rowBase = blockIdx.x * 128;

    // ---- stage u tile (tf32-rounded), coalesced float4 ----
    {
        const float4* ug = (const float4*)(u + (long long)rowBase * ND);
#pragma unroll
        for (int i = 0; i < 16; i++) {
            int idx = t + i * 256;          // 0..4095
            int row = idx >> 5, c4 = idx & 31;
            float4 v = ug[idx];
            v.x = tfr(v.x); v.y = tfr(v.y); v.z = tfr(v.z); v.w = tfr(v.w);
            *(float4*)(sU + row * PAD + c4 * 4) = v;
        }
    }
    __syncthreads();

    const int wid = t >> 5, lane = t & 31;
    const int warpM = wid >> 1, warpE = wid & 1;
    const int g = lane >> 2, tg = lane & 3;

    float acc[2][8][4];
#pragma unroll
    for (int mt = 0; mt < 2; mt++)
#pragma unroll
        for (int nt = 0; nt < 8; nt++)
#pragma unroll
            for (int r = 0; r < 4; r++) acc[mt][nt][r] = 0.f;

    const float*  Abase = sU + (warpM * 32 + g) * PAD + tg;
    const float4* Bbase = g_W1f + warpE * 2048 + g * 4 + tg;

#pragma unroll 4
    for (int ks = 0; ks < 16; ks++) {
        const int kc = ks * 8;
        uint32_t a[2][4];
#pragma unroll
        for (int mt = 0; mt < 2; mt++) {
            const float* ar = Abase + mt * 16 * PAD + kc;
            a[mt][0] = __float_as_uint(ar[0]);
            a[mt][1] = __float_as_uint(ar[8 * PAD]);
            a[mt][2] = __float_as_uint(ar[4]);
            a[mt][3] = __float_as_uint(ar[8 * PAD + 4]);
        }
#pragma unroll
        for (int ntp = 0; ntp < 4; ntp++) {
            float4 bb = Bbase[ntp * 512 + ks * 32];
            uint32_t blo0 = __float_as_uint(bb.x), blo1 = __float_as_uint(bb.y);
            uint32_t bhi0 = __float_as_uint(bb.z), bhi1 = __float_as_uint(bb.w);
            mma_tf32(acc[0][2 * ntp + 0], a[0], blo0, blo1);
            mma_tf32(acc[1][2 * ntp + 0], a[1], blo0, blo1);
            mma_tf32(acc[0][2 * ntp + 1], a[0], bhi0, bhi1);
            mma_tf32(acc[1][2 * ntp + 1], a[1], bhi0, bhi1);
        }
    }

    // ---- epilogue: + b1 + mask*z3 + (c==mycol)*z2 ; residual already folded ----
    const int node = blockIdx.x * 4 + warpM;
    const int mycol = __ldg(coloring + node);
    const float* z2p = g_z2 + node * ND;
    const float* z3p = g_z3 + node * ND;

    float mk[2][2];
    bool  hit[2][2];
    int   grow[2][2];
#pragma unroll
    for (int mt = 0; mt < 2; mt++)
#pragma unroll
        for (int half = 0; half < 2; half++) {
            int c = mt * 16 + half * 8 + g;
            grow[mt][half] = rowBase + warpM * 32 + c;
            mk[mt][half]  = __ldg(mask + grow[mt][half]);
            hit[mt][half] = (c == mycol);
        }

#pragma unroll
    for (int nt = 0; nt < 8; nt++) {
        const int e = warpE * 64 + nt * 8 + tg * 2;
        const float2 bv  = *(const float2*)(b1  + e);
        const float2 z2v = *(const float2*)(z2p + e);
        const float2 z3v = *(const float2*)(z3p + e);
#pragma unroll
        for (int mt = 0; mt < 2; mt++)
#pragma unroll
            for (int half = 0; half < 2; half++) {
                float v0 = acc[mt][nt][half * 2 + 0] + bv.x + mk[mt][half] * z3v.x;
                float v1 = acc[mt][nt][half * 2 + 1] + bv.y + mk[mt][half] * z3v.y;
                if (hit[mt][half]) { v0 += z2v.x; v1 += z2v.y; }
                *(float2*)(out + (long long)grow[mt][half] * ND + e) = make_float2(v0, v1);
            }
    }
}

// ============================================================================
extern "C" void kernel_launch(void* const* d_in, const int* in_sizes, int n_in,
                              void* d_out, int out_size) {
    const float* u    = (const float*)d_in[0];
    const float* mask = (const float*)d_in[1];
    const float* norm = (const float*)d_in[2];
    const int*   col  = (const int*)d_in[3];
    const float* W1   = (const float*)d_in[4];
    const float* b1   = (const float*)d_in[5];
    const float* W2   = (const float*)d_in[6];
    const float* W3   = (const float*)d_in[7];
    float* out = (float*)d_out;

    static bool attr_set = false;
    if (!attr_set) {
        cudaFuncSetAttribute(main_gemm_kernel,
                             cudaFuncAttributeMaxDynamicSharedMemorySize,
                             128 * PAD * sizeof(float));
        attr_set = true;
    }

    prep_kernel<<<16, 256>>>(W1, W2, W3);
    mean_z_kernel<<<NNODES / 8, 256>>>(u, norm);
    main_gemm_kernel<<<NNODES / 4, 256, 128 * PAD * sizeof(float)>>>(
        u, mask, col, b1, out);

    (void)in_sizes; (void)n_in; (void)out_size;
}

// round 3
// speedup vs baseline: 2.8990x; 1.2247x over previous
#include <cuda_runtime.h>
#include <cstdint>

#define NNODES 20000
#define NC 32
#define ND 128
#define PAD 132   // padded smem row (floats): conflict-free fragment reads

// ---- device scratch (static globals only; no runtime alloc) ----
__device__ float4 g_W1f[4096];        // paired-permuted tf32(W1 + I)   (64 KB)
__device__ float4 g_W23f[8192];       // paired-permuted tf32([W2;W3])  (128 KB)

// Smem layout (floats)
#define OFF_U     0
#define OFF_MEAN  (128 * PAD)               // 16896
#define OFF_Z2    (OFF_MEAN + 4 * PAD)      // 17424
#define OFF_Z3    (OFF_Z2 + 4 * ND)         // 17936
#define SMEM_FLOATS (OFF_Z3 + 4 * ND)       // 18448
#define SMEM_BYTES  (SMEM_FLOATS * 4)       // 73792

__device__ __forceinline__ float tfr(float x) {
    uint32_t r;
    asm("cvt.rna.tf32.f32 %0, %1;" : "=r"(r) : "f"(x));
    return __uint_as_float(r);
}

__device__ __forceinline__ void mma_tf32(float* d, const uint32_t* a,
                                         uint32_t b0, uint32_t b1) {
    asm volatile(
        "mma.sync.aligned.m16n8k8.row.col.f32.tf32.tf32.f32 "
        "{%0,%1,%2,%3}, {%4,%5,%6,%7}, {%8,%9}, {%0,%1,%2,%3};\n"
        : "+f"(d[0]), "+f"(d[1]), "+f"(d[2]), "+f"(d[3])
        : "r"(a[0]), "r"(a[1]), "r"(a[2]), "r"(a[3]), "r"(b0), "r"(b1));
}

// ============================================================================
// Kernel 0: build fragment-permuted tf32 weight buffers (runs once, ~6us).
// For a warp, one (n-tile-pair, ks) slice is a contiguous 512B block.
// ============================================================================
__global__ void prep_kernel(const float* __restrict__ W1,
                            const float* __restrict__ W2,
                            const float* __restrict__ W3) {
    int t0 = blockIdx.x * blockDim.x + threadIdx.x;
    int stride = gridDim.x * blockDim.x;
    // g_W1f[i], i = wE*2048 + ntp*512 + ks*32 + g*4 + tg   (W1 + I folded)
    for (int i = t0; i < 4096; i += stride) {
        int tg = i & 3, g = (i >> 2) & 7, ks = (i >> 5) & 15;
        int ntp = (i >> 9) & 3, wE = (i >> 11) & 1;
        int e0 = wE * 64 + ntp * 16 + g, e1 = e0 + 8;
        int k0 = ks * 8 + tg, k1 = k0 + 4;
        g_W1f[i] = make_float4(
            tfr(W1[e0 * ND + k0] + (e0 == k0 ? 1.f : 0.f)),
            tfr(W1[e0 * ND + k1] + (e0 == k1 ? 1.f : 0.f)),
            tfr(W1[e1 * ND + k0] + (e1 == k0 ? 1.f : 0.f)),
            tfr(W1[e1 * ND + k1] + (e1 == k1 ? 1.f : 0.f)));
    }
    // g_W23f[i], i = w*1024 + ntp*512 + ks*32 + g*4 + tg ; rows e: [W2 | W3]
    for (int i = t0; i < 8192; i += stride) {
        int tg = i & 3, g = (i >> 2) & 7, ks = (i >> 5) & 15;
        int ntp = (i >> 9) & 1, w = (i >> 10) & 7;
        int e0 = w * 32 + ntp * 16 + g, e1 = e0 + 8;
        int k0 = ks * 8 + tg, k1 = k0 + 4;
        const float* r0 = (e0 < 128) ? (W2 + e0 * ND) : (W3 + (e0 - 128) * ND);
        const float* r1 = (e1 < 128) ? (W2 + e1 * ND) : (W3 + (e1 - 128) * ND);
        g_W23f[i] = make_float4(tfr(r0[k0]), tfr(r0[k1]), tfr(r1[k0]), tfr(r1[k1]));
    }
}

// ============================================================================
// Fused kernel: per CTA of 4 nodes (128 rows):
//   stage u -> mean over colors -> z2/z3 (tiny padded tensor GEMM, smem) ->
//   main GEMM out = u @ tf32(W1+I)^T -> epilogue (+b1 +mask*z3 +color-hit z2)
// u is read from DRAM exactly once; residual folded into W1.
// ============================================================================
__global__ void __launch_bounds__(256, 2)
fused_kernel(const float* __restrict__ u,
             const float* __restrict__ mask,
             const float* __restrict__ normalizer,
             const int* __restrict__ coloring,
             const float* __restrict__ b1,
             float* __restrict__ out) {
    extern __shared__ float sm[];
    float* sU    = sm + OFF_U;
    float* smean = sm + OFF_MEAN;
    float* sZ2   = sm + OFF_Z2;
    float* sZ3   = sm + OFF_Z3;

    const int t = threadIdx.x;
    const int rowBase = blockIdx.x * 128;
    const int nodeBase = blockIdx.x * 4;

    // ---- stage u tile (tf32-rounded), coalesced float4 ----
    {
        const float4* ug = (const float4*)(u + (long long)rowBase * ND);
#pragma unroll
        for (int i = 0; i < 16; i++) {
            int idx = t + i * 256;          // 0..4095
            int row = idx >> 5, c4 = idx & 31;
            float4 v = ug[idx];
            v.x = tfr(v.x); v.y = tfr(v.y); v.z = tfr(v.z); v.w = tfr(v.w);
            *(float4*)(sU + row * PAD + c4 * 4) = v;
        }
    }
    __syncthreads();

    // ---- mean over colors, per node, from smem (conflict-free) ----
    {
        int i = t >> 6;            // node in block, warp-aligned (2 warps/node)
        int d = t & 63;
        float inv = 1.f / normalizer[nodeBase + i];
        const float* base = sU + (i * 32) * PAD;
#pragma unroll
        for (int rep = 0; rep < 2; rep++) {
            int dd = d + rep * 64;
            float s = 0.f;
#pragma unroll
            for (int c = 0; c < NC; c++) s += base[c * PAD + dd];
            smean[i * PAD + dd] = tfr(s * inv);
        }
    }
    __syncthreads();

    const int wid = t >> 5, lane = t & 31;
    const int g = lane >> 2, tg = lane & 3;

    // ---- z = mean(4x128, M-padded to 16) @ W23^T(256x128), scatter to smem ----
    {
        float zacc[4][4];
#pragma unroll
        for (int n = 0; n < 4; n++)
#pragma unroll
            for (int r = 0; r < 4; r++) zacc[n][r] = 0.f;

        const float4* Bp = g_W23f + wid * 1024 + g * 4 + tg;
        const float* Ab = smean + g * PAD + tg;   // rows g>=4 are padding
        const bool valid = (g < 4);
#pragma unroll
        for (int ks = 0; ks < 16; ks++) {
            const int kc = ks * 8;
            uint32_t a[4];
            a[0] = valid ? __float_as_uint(Ab[kc]) : 0u;
            a[1] = 0u;
            a[2] = valid ? __float_as_uint(Ab[kc + 4]) : 0u;
            a[3] = 0u;
#pragma unroll
            for (int ntp = 0; ntp < 2; ntp++) {
                float4 bb = Bp[ntp * 512 + ks * 32];
                mma_tf32(zacc[2 * ntp + 0], a, __float_as_uint(bb.x), __float_as_uint(bb.y));
                mma_tf32(zacc[2 * ntp + 1], a, __float_as_uint(bb.z), __float_as_uint(bb.w));
            }
        }
        if (valid) {
            const int node = g;   // local node index
#pragma unroll
            for (int nt = 0; nt < 4; nt++) {
                int e = wid * 32 + nt * 8 + tg * 2;
                float2 v = make_float2(0.1f * zacc[nt][0], 0.1f * zacc[nt][1]);
                if (e < 128) *(float2*)(sZ2 + node * ND + e) = v;
                else         *(float2*)(sZ3 + node * ND + (e - 128)) = v;
            }
        }
    }
    // (no barrier yet: sZ consumed only after the post-GEMM barrier)

    // ---- main GEMM: [128 x 128] = sU @ tf32(W1+I)^T ----
    const int warpM = wid >> 1, warpE = wid & 1;

    float acc[2][8][4];
#pragma unroll
    for (int mt = 0; mt < 2; mt++)
#pragma unroll
        for (int nt = 0; nt < 8; nt++)
#pragma unroll
            for (int r = 0; r < 4; r++) acc[mt][nt][r] = 0.f;

    const float*  Abase = sU + (warpM * 32 + g) * PAD + tg;
    const float4* Bbase = g_W1f + warpE * 2048 + g * 4 + tg;

#pragma unroll 4
    for (int ks = 0; ks < 16; ks++) {
        const int kc = ks * 8;
        uint32_t a[2][4];
#pragma unroll
        for (int mt = 0; mt < 2; mt++) {
            const float* ar = Abase + mt * 16 * PAD + kc;
            a[mt][0] = __float_as_uint(ar[0]);
            a[mt][1] = __float_as_uint(ar[8 * PAD]);
            a[mt][2] = __float_as_uint(ar[4]);
            a[mt][3] = __float_as_uint(ar[8 * PAD + 4]);
        }
#pragma unroll
        for (int ntp = 0; ntp < 4; ntp++) {
            float4 bb = Bbase[ntp * 512 + ks * 32];
            uint32_t blo0 = __float_as_uint(bb.x), blo1 = __float_as_uint(bb.y);
            uint32_t bhi0 = __float_as_uint(bb.z), bhi1 = __float_as_uint(bb.w);
            mma_tf32(acc[0][2 * ntp + 0], a[0], blo0, blo1);
            mma_tf32(acc[1][2 * ntp + 0], a[1], blo0, blo1);
            mma_tf32(acc[0][2 * ntp + 1], a[0], bhi0, bhi1);
            mma_tf32(acc[1][2 * ntp + 1], a[1], bhi0, bhi1);
        }
    }

    __syncthreads();   // sZ2/sZ3 now visible to all warps

    // ---- epilogue: + b1 + mask*z3 + (c==mycol)*z2 (residual already folded) ----
    const int node = nodeBase + warpM;
    const int mycol = __ldg(coloring + node);
    const float* z2p = sZ2 + warpM * ND;
    const float* z3p = sZ3 + warpM * ND;

    float mk[2][2];
    bool  hit[2][2];
    int   grow[2][2];
#pragma unroll
    for (int mt = 0; mt < 2; mt++)
#pragma unroll
        for (int half = 0; half < 2; half++) {
            int c = mt * 16 + half * 8 + g;
            grow[mt][half] = rowBase + warpM * 32 + c;
            mk[mt][half]  = __ldg(mask + grow[mt][half]);
            hit[mt][half] = (c == mycol);
        }

#pragma unroll
    for (int nt = 0; nt < 8; nt++) {
        const int e = warpE * 64 + nt * 8 + tg * 2;
        const float2 bv  = *(const float2*)(b1  + e);
        const float2 z2v = *(const float2*)(z2p + e);
        const float2 z3v = *(const float2*)(z3p + e);
#pragma unroll
        for (int mt = 0; mt < 2; mt++)
#pragma unroll
            for (int half = 0; half < 2; half++) {
                float v0 = acc[mt][nt][half * 2 + 0] + bv.x + mk[mt][half] * z3v.x;
                float v1 = acc[mt][nt][half * 2 + 1] + bv.y + mk[mt][half] * z3v.y;
                if (hit[mt][half]) { v0 += z2v.x; v1 += z2v.y; }
                *(float2*)(out + (long long)grow[mt][half] * ND + e) = make_float2(v0, v1);
            }
    }
}

// ============================================================================
extern "C" void kernel_launch(void* const* d_in, const int* in_sizes, int n_in,
                              void* d_out, int out_size) {
    const float* u    = (const float*)d_in[0];
    const float* mask = (const float*)d_in[1];
    const float* norm = (const float*)d_in[2];
    const int*   col  = (const int*)d_in[3];
    const float* W1   = (const float*)d_in[4];
    const float* b1   = (const float*)d_in[5];
    const float* W2   = (const float*)d_in[6];
    const float* W3   = (const float*)d_in[7];
    float* out = (float*)d_out;

    static bool attr_set = false;
    if (!attr_set) {
        cudaFuncSetAttribute(fused_kernel,
                             cudaFuncAttributeMaxDynamicSharedMemorySize,
                             SMEM_BYTES);
        attr_set = true;
    }

    prep_kernel<<<16, 256>>>(W1, W2, W3);
    fused_kernel<<<NNODES / 4, 256, SMEM_BYTES>>>(u, mask, norm, col, b1, out);

    (void)in_sizes; (void)n_in; (void)out_size;
}

// round 5
// speedup vs baseline: 3.0755x; 1.0609x over previous
#include <cuda_runtime.h>
#include <cuda_fp16.h>
#include <cstdint>

#define NNODES 20000
#define NC 32
#define ND 128
#define PADF 136        // fp32 smem row pitch (floats): float4-aligned, conflict-free
#define ROWH 272        // fp16 smem row pitch in BYTES (136 halfs)

// ---- smem byte offsets ----
#define SUF 0                    // fp32 u tile 128 x 136 x 4 = 69632
#define SUH 69632                // fp16 u tile 128 x 272     = 34816
#define SMH 104448               // fp16 mean 4 x 272         = 1088
#define SZ2 105536               // fp32 z2 4 x 128 x 4       = 2048
#define SZ3 107584               // fp32 z3                   = 2048
#define SB1 109632               // fp32 b1                   = 512
#define SMEM_BYTES 110144        // x2 CTAs = 220288 <= 228KB/SM

// ---- device scratch: fragment-permuted fp16 weights ----
// g_W1h[wE*1024 + ntp*256 + ks*32 + lane]: lane=(g*4+tg)
//   .x = {W1[e][kb], W1[e][kb+1]}  .y = {W1[e][kb+8], W1[e][kb+9]}
//   .z/.w same for e+8;  e = wE*64+ntp*16+g, kb = ks*16+2tg
__device__ uint4 g_W1h[2048];    // 32 KB
// g_W23h[w*512 + ntp*256 + ks*32 + lane]; rows e: [W2 | W3], e = w*32+ntp*16+g
__device__ uint4 g_W23h[4096];   // 64 KB

__device__ __forceinline__ uint32_t pk(float a, float b) {
    __half2 h = __floats2half2_rn(a, b);
    return *(uint32_t*)&h;
}

__device__ __forceinline__ void mma_f16(float* d, const uint32_t* a,
                                        uint32_t b0, uint32_t b1) {
    asm volatile(
        "mma.sync.aligned.m16n8k16.row.col.f32.f16.f16.f32 "
        "{%0,%1,%2,%3}, {%4,%5,%6,%7}, {%8,%9}, {%0,%1,%2,%3};\n"
        : "+f"(d[0]), "+f"(d[1]), "+f"(d[2]), "+f"(d[3])
        : "r"(a[0]), "r"(a[1]), "r"(a[2]), "r"(a[3]), "r"(b0), "r"(b1));
}

// ============================================================================
// prep: build fragment-permuted fp16 weight images (runs once, ~5us)
// ============================================================================
__global__ void prep_kernel(const float* __restrict__ W1,
                            const float* __restrict__ W2,
                            const float* __restrict__ W3) {
    int t0 = blockIdx.x * blockDim.x + threadIdx.x;
    int stride = gridDim.x * blockDim.x;
    for (int i = t0; i < 2048; i += stride) {
        int lane = i & 31, ks = (i >> 5) & 7, ntp = (i >> 8) & 3, wE = i >> 10;
        int g = lane >> 2, tg = lane & 3;
        int e0 = wE * 64 + ntp * 16 + g, e1 = e0 + 8;
        int kb = ks * 16 + 2 * tg;
        uint4 v;
        v.x = pk(W1[e0 * ND + kb],     W1[e0 * ND + kb + 1]);
        v.y = pk(W1[e0 * ND + kb + 8], W1[e0 * ND + kb + 9]);
        v.z = pk(W1[e1 * ND + kb],     W1[e1 * ND + kb + 1]);
        v.w = pk(W1[e1 * ND + kb + 8], W1[e1 * ND + kb + 9]);
        g_W1h[i] = v;
    }
    for (int i = t0; i < 4096; i += stride) {
        int lane = i & 31, ks = (i >> 5) & 7, ntp = (i >> 8) & 1, w = i >> 9;
        int g = lane >> 2, tg = lane & 3;
        int e0 = w * 32 + ntp * 16 + g, e1 = e0 + 8;
        int kb = ks * 16 + 2 * tg;
        const float* r0 = (e0 < 128) ? (W2 + e0 * ND) : (W3 + (e0 - 128) * ND);
        const float* r1 = (e1 < 128) ? (W2 + e1 * ND) : (W3 + (e1 - 128) * ND);
        uint4 v;
        v.x = pk(r0[kb], r0[kb + 1]);
        v.y = pk(r0[kb + 8], r0[kb + 9]);
        v.z = pk(r1[kb], r1[kb + 1]);
        v.w = pk(r1[kb + 8], r1[kb + 9]);
        g_W23h[i] = v;
    }
}

// ============================================================================
// Fused kernel: 4 nodes (128 rows) per CTA, 256 threads, 2 CTAs/SM.
//   stage u (fp32 + fp16) -> mean (from fp16 tile) -> z2/z3 (fp16 mma) ->
//   main GEMM fp16 m16n8k16 -> epilogue (fp32 residual + b1 + mask*z3 + z2)
// ============================================================================
__global__ void __launch_bounds__(256, 2)
fused_kernel(const float* __restrict__ u,
             const float* __restrict__ mask,
             const float* __restrict__ normalizer,
             const int* __restrict__ coloring,
             const float* __restrict__ b1,
             float* __restrict__ out) {
    extern __shared__ char smem[];
    float* sUf = (float*)(smem + SUF);
    float* sZ2 = (float*)(smem + SZ2);
    float* sZ3 = (float*)(smem + SZ3);
    float* sB1 = (float*)(smem + SB1);

    const int t = threadIdx.x;
    const int rowBase = blockIdx.x * 128;
    const int nodeBase = blockIdx.x * 4;

    // ---- stage u: fp32 tile + fp16 tile, coalesced float4 ----
    {
        const float4* ug = (const float4*)(u + (long long)rowBase * ND);
#pragma unroll
        for (int i = 0; i < 16; i++) {
            int idx = t + i * 256;              // 0..4095
            int row = idx >> 5, c4 = idx & 31;
            float4 v = ug[idx];
            *(float4*)(sUf + row * PADF + c4 * 4) = v;
            uint2 h;
            h.x = pk(v.x, v.y);
            h.y = pk(v.z, v.w);
            *(uint2*)(smem + SUH + row * ROWH + c4 * 8) = h;
        }
    }
    if (t < 32) *(float4*)(sB1 + t * 4) = ((const float4*)b1)[t];
    __syncthreads();

    // ---- mean over colors from fp16 tile (uint = 2 halfs per load) ----
    {
        int node = t >> 6, dp = t & 63;        // dp = pair of channels
        float inv = 1.f / normalizer[nodeBase + node];
        const char* base = smem + SUH + (node * 32) * ROWH + dp * 4;
        float sx = 0.f, sy = 0.f;
#pragma unroll
        for (int c = 0; c < NC; c++) {
            __half2 h = *(const __half2*)(base + c * ROWH);
            float2 f = __half22float2(h);
            sx += f.x; sy += f.y;
        }
        *(uint32_t*)(smem + SMH + node * ROWH + dp * 4) = pk(sx * inv, sy * inv);
    }
    __syncthreads();

    const int w = t >> 5, lane = t & 31;
    const int g = lane >> 2, tg = lane & 3;

    // ---- z2/z3: mean(4x128, M-pad 16) @ [W2;W3]^T via fp16 mma ----
    {
        float zacc[4][4];
#pragma unroll
        for (int n = 0; n < 4; n++)
#pragma unroll
            for (int r = 0; r < 4; r++) zacc[n][r] = 0.f;

        const uint4* Bp = g_W23h + w * 512 + lane;
        const char* Ab = smem + SMH + g * ROWH + tg * 4;
        const bool valid = (g < 4);
#pragma unroll
        for (int ks = 0; ks < 8; ks++) {
            uint32_t a[4];
            a[0] = valid ? *(const uint32_t*)(Ab + ks * 32) : 0u;
            a[1] = 0u;                          // rows 8..15 padding
            a[2] = valid ? *(const uint32_t*)(Ab + ks * 32 + 16) : 0u;
            a[3] = 0u;
#pragma unroll
            for (int ntp = 0; ntp < 2; ntp++) {
                uint4 bb = Bp[ntp * 256 + ks * 32];
                mma_f16(zacc[2 * ntp + 0], a, bb.x, bb.y);
                mma_f16(zacc[2 * ntp + 1], a, bb.z, bb.w);
            }
        }
        if (valid) {
#pragma unroll
            for (int nt = 0; nt < 4; nt++) {
                int e = w * 32 + nt * 8 + tg * 2;
                float2 v = make_float2(0.1f * zacc[nt][0], 0.1f * zacc[nt][1]);
                if (e < 128) *(float2*)(sZ2 + g * ND + e) = v;
                else         *(float2*)(sZ3 + g * ND + (e - 128)) = v;
            }
        }
    }
    // (no barrier: sZ consumed after the post-GEMM barrier)

    // ---- main GEMM: [128 x 128] = fp16(u) @ fp16(W1)^T ----
    const int warpM = w >> 1, warpE = w & 1;

    float acc[2][8][4];
#pragma unroll
    for (int mt = 0; mt < 2; mt++)
#pragma unroll
        for (int nt = 0; nt < 8; nt++)
#pragma unroll
            for (int r = 0; r < 4; r++) acc[mt][nt][r] = 0.f;

    const char*  Abase = smem + SUH + (warpM * 32 + g) * ROWH + tg * 4;
    const uint4* Bbase = g_W1h + warpE * 1024 + lane;

#pragma unroll
    for (int ks = 0; ks < 8; ks++) {
        uint32_t a[2][4];
#pragma unroll
        for (int mt = 0; mt < 2; mt++) {
            const char* ar = Abase + mt * 16 * ROWH + ks * 32;
            a[mt][0] = *(const uint32_t*)(ar);
            a[mt][1] = *(const uint32_t*)(ar + 8 * ROWH);
            a[mt][2] = *(const uint32_t*)(ar + 16);
            a[mt][3] = *(const uint32_t*)(ar + 8 * ROWH + 16);
        }
#pragma unroll
        for (int ntp = 0; ntp < 4; ntp++) {
            uint4 bb = Bbase[ntp * 256 + ks * 32];
            mma_f16(acc[0][2 * ntp + 0], a[0], bb.x, bb.y);
            mma_f16(acc[1][2 * ntp + 0], a[1], bb.x, bb.y);
            mma_f16(acc[0][2 * ntp + 1], a[0], bb.z, bb.w);
            mma_f16(acc[1][2 * ntp + 1], a[1], bb.z, bb.w);
        }
    }

    __syncthreads();   // sZ2/sZ3 visible

    // ---- epilogue: + u(fp32) + b1 + mask*z3 + (c==mycol)*z2 ----
    const int node = warpM;
    const int mycol = __ldg(coloring + nodeBase + node);
    const float* z2p = sZ2 + node * ND;
    const float* z3p = sZ3 + node * ND;

    float mk[2][2];
    bool  hit[2][2];
    int   lrow[2][2];
#pragma unroll
    for (int mt = 0; mt < 2; mt++)
#pragma unroll
        for (int half = 0; half < 2; half++) {
            int c = mt * 16 + half * 8 + g;
            lrow[mt][half] = warpM * 32 + c;
            mk[mt][half]  = __ldg(mask + rowBase + lrow[mt][half]);
            hit[mt][half] = (c == mycol);
        }

#pragma unroll
    for (int nt = 0; nt < 8; nt++) {
        const int e = warpE * 64 + nt * 8 + tg * 2;
        const float2 bv  = *(const float2*)(sB1 + e);
        const float2 z2v = *(const float2*)(z2p + e);
        const float2 z3v = *(const float2*)(z3p + e);
#pragma unroll
        for (int mt = 0; mt < 2; mt++)
#pragma unroll
            for (int half = 0; half < 2; half++) {
                const int r = lrow[mt][half];
                const float2 uv = *(const float2*)(sUf + r * PADF + e);
                float v0 = acc[mt][nt][half * 2 + 0] + uv.x + bv.x + mk[mt][half] * z3v.x;
                float v1 = acc[mt][nt][half * 2 + 1] + uv.y + bv.y + mk[mt][half] * z3v.y;
                if (hit[mt][half]) { v0 += z2v.x; v1 += z2v.y; }
                *(float2*)(out + (long long)(rowBase + r) * ND + e) =
                    make_float2(v0, v1);
            }
    }
}

// ============================================================================
extern "C" void kernel_launch(void* const* d_in, const int* in_sizes, int n_in,
                              void* d_out, int out_size) {
    const float* u    = (const float*)d_in[0];
    const float* mask = (const float*)d_in[1];
    const float* norm = (const float*)d_in[2];
    const int*   col  = (const int*)d_in[3];
    const float* W1   = (const float*)d_in[4];
    const float* b1   = (const float*)d_in[5];
    const float* W2   = (const float*)d_in[6];
    const float* W3   = (const float*)d_in[7];
    float* out = (float*)d_out;

    static bool attr_set = false;
    if (!attr_set) {
        cudaFuncSetAttribute(fused_kernel,
                             cudaFuncAttributeMaxDynamicSharedMemorySize,
                             SMEM_BYTES);
        attr_set = true;
    }

    prep_kernel<<<24, 256>>>(W1, W2, W3);
    fused_kernel<<<NNODES / 4, 256, SMEM_BYTES>>>(u, mask, norm, col, b1, out);

    (void)in_sizes; (void)n_in; (void)out_size;
}

// round 6
// speedup vs baseline: 4.0851x; 1.3283x over previous
#include <cuda_runtime.h>
#include <cuda_fp16.h>
#include <cstdint>

#define NNODES 20000
#define NC 32
#define ND 128
#define ROWH 272        // fp16 smem row pitch in BYTES (136 halfs): conflict-free

// ---- smem byte offsets ----
#define SUH 0                    // fp16 u tile 128 x 272     = 34816
#define SMH 34816                // fp16 mean 4 x 272         = 1088
#define SZ2 35904                // fp32 z2 4 x 128 x 4       = 2048
#define SZ3 37952                // fp32 z3                   = 2048
#define SB1 40000                // fp32 b1                   = 512
#define SMEM_BYTES 40512

// ---- device scratch: fragment-permuted fp16 weights ----
// g_W1h[wE*1024 + ntp*256 + ks*32 + lane]: lane=(g*4+tg)
//   .x = {M[e][kb], M[e][kb+1]}  .y = {M[e][kb+8], M[e][kb+9]}  (M = W1 + I)
//   .z/.w same for e+8;  e = wE*64+ntp*16+g, kb = ks*16+2tg
__device__ uint4 g_W1h[2048];    // 32 KB
// g_W23h[w*512 + ntp*256 + ks*32 + lane]; rows e: [W2 | W3], e = w*32+ntp*16+g
__device__ uint4 g_W23h[4096];   // 64 KB

__device__ __forceinline__ uint32_t pk(float a, float b) {
    __half2 h = __floats2half2_rn(a, b);
    return *(uint32_t*)&h;
}

__device__ __forceinline__ void mma_f16(float* d, const uint32_t* a,
                                        uint32_t b0, uint32_t b1) {
    asm volatile(
        "mma.sync.aligned.m16n8k16.row.col.f32.f16.f16.f32 "
        "{%0,%1,%2,%3}, {%4,%5,%6,%7}, {%8,%9}, {%0,%1,%2,%3};\n"
        : "+f"(d[0]), "+f"(d[1]), "+f"(d[2]), "+f"(d[3])
        : "r"(a[0]), "r"(a[1]), "r"(a[2]), "r"(a[3]), "r"(b0), "r"(b1));
}

// ============================================================================
// prep: fragment-permuted fp16 weight images; W1 gets +I (residual folded)
// ============================================================================
__global__ void prep_kernel(const float* __restrict__ W1,
                            const float* __restrict__ W2,
                            const float* __restrict__ W3) {
    int t0 = blockIdx.x * blockDim.x + threadIdx.x;
    int stride = gridDim.x * blockDim.x;
    for (int i = t0; i < 2048; i += stride) {
        int lane = i & 31, ks = (i >> 5) & 7, ntp = (i >> 8) & 3, wE = i >> 10;
        int g = lane >> 2, tg = lane & 3;
        int e0 = wE * 64 + ntp * 16 + g, e1 = e0 + 8;
        int kb = ks * 16 + 2 * tg;
        uint4 v;
        v.x = pk(W1[e0 * ND + kb]     + (e0 == kb     ? 1.f : 0.f),
                 W1[e0 * ND + kb + 1] + (e0 == kb + 1 ? 1.f : 0.f));
        v.y = pk(W1[e0 * ND + kb + 8] + (e0 == kb + 8 ? 1.f : 0.f),
                 W1[e0 * ND + kb + 9] + (e0 == kb + 9 ? 1.f : 0.f));
        v.z = pk(W1[e1 * ND + kb]     + (e1 == kb     ? 1.f : 0.f),
                 W1[e1 * ND + kb + 1] + (e1 == kb + 1 ? 1.f : 0.f));
        v.w = pk(W1[e1 * ND + kb + 8] + (e1 == kb + 8 ? 1.f : 0.f),
                 W1[e1 * ND + kb + 9] + (e1 == kb + 9 ? 1.f : 0.f));
        g_W1h[i] = v;
    }
    for (int i = t0; i < 4096; i += stride) {
        int lane = i & 31, ks = (i >> 5) & 7, ntp = (i >> 8) & 1, w = i >> 9;
        int g = lane >> 2, tg = lane & 3;
        int e0 = w * 32 + ntp * 16 + g, e1 = e0 + 8;
        int kb = ks * 16 + 2 * tg;
        const float* r0 = (e0 < 128) ? (W2 + e0 * ND) : (W3 + (e0 - 128) * ND);
        const float* r1 = (e1 < 128) ? (W2 + e1 * ND) : (W3 + (e1 - 128) * ND);
        uint4 v;
        v.x = pk(r0[kb], r0[kb + 1]);
        v.y = pk(r0[kb + 8], r0[kb + 9]);
        v.z = pk(r1[kb], r1[kb + 1]);
        v.w = pk(r1[kb + 8], r1[kb + 9]);
        g_W23h[i] = v;
    }
}

// ============================================================================
// Fused kernel: 4 nodes (128 rows) per CTA, 256 threads, 2 CTAs/SM.
//   stage fp16(u) -> mean -> z2/z3 (fp16 mma) -> main GEMM fp16(u)@fp16(W1+I)^T
//   -> epilogue (+b1 +mask*z3 +color-hit z2); residual folded into W1.
// ============================================================================
__global__ void __launch_bounds__(256, 2)
fused_kernel(const float* __restrict__ u,
             const float* __restrict__ mask,
             const float* __restrict__ normalizer,
             const int* __restrict__ coloring,
             const float* __restrict__ b1,
             float* __restrict__ out) {
    extern __shared__ char smem[];
    float* sZ2 = (float*)(smem + SZ2);
    float* sZ3 = (float*)(smem + SZ3);
    float* sB1 = (float*)(smem + SB1);

    const int t = threadIdx.x;
    const int rowBase = blockIdx.x * 128;
    const int nodeBase = blockIdx.x * 4;

    // ---- stage u -> fp16 tile, coalesced float4 loads, STS.64 ----
    {
        const float4* ug = (const float4*)(u + (long long)rowBase * ND);
#pragma unroll
        for (int i = 0; i < 16; i++) {
            int idx = t + i * 256;              // 0..4095
            int row = idx >> 5, c4 = idx & 31;
            float4 v = ug[idx];
            uint2 h;
            h.x = pk(v.x, v.y);
            h.y = pk(v.z, v.w);
            *(uint2*)(smem + SUH + row * ROWH + c4 * 8) = h;
        }
    }
    if (t < 32) *(float4*)(sB1 + t * 4) = ((const float4*)b1)[t];
    __syncthreads();

    // ---- mean over colors from fp16 tile ----
    {
        int node = t >> 6, dp = t & 63;        // dp = channel pair
        float inv = 1.f / normalizer[nodeBase + node];
        const char* base = smem + SUH + (node * 32) * ROWH + dp * 4;
        float sx = 0.f, sy = 0.f;
#pragma unroll
        for (int c = 0; c < NC; c++) {
            __half2 h = *(const __half2*)(base + c * ROWH);
            float2 f = __half22float2(h);
            sx += f.x; sy += f.y;
        }
        *(uint32_t*)(smem + SMH + node * ROWH + dp * 4) = pk(sx * inv, sy * inv);
    }
    __syncthreads();

    const int w = t >> 5, lane = t & 31;
    const int g = lane >> 2, tg = lane & 3;

    // ---- z2/z3: mean(4x128, M-pad 16) @ [W2;W3]^T via fp16 mma ----
    {
        float zacc[4][4];
#pragma unroll
        for (int n = 0; n < 4; n++)
#pragma unroll
            for (int r = 0; r < 4; r++) zacc[n][r] = 0.f;

        const uint4* Bp = g_W23h + w * 512 + lane;
        const char* Ab = smem + SMH + g * ROWH + tg * 4;
        const bool valid = (g < 4);
#pragma unroll
        for (int ks = 0; ks < 8; ks++) {
            uint32_t a[4];
            a[0] = valid ? *(const uint32_t*)(Ab + ks * 32) : 0u;
            a[1] = 0u;                          // rows 8..15 padding
            a[2] = valid ? *(const uint32_t*)(Ab + ks * 32 + 16) : 0u;
            a[3] = 0u;
#pragma unroll
            for (int ntp = 0; ntp < 2; ntp++) {
                uint4 bb = Bp[ntp * 256 + ks * 32];
                mma_f16(zacc[2 * ntp + 0], a, bb.x, bb.y);
                mma_f16(zacc[2 * ntp + 1], a, bb.z, bb.w);
            }
        }
        if (valid) {
#pragma unroll
            for (int nt = 0; nt < 4; nt++) {
                int e = w * 32 + nt * 8 + tg * 2;
                float2 v = make_float2(0.1f * zacc[nt][0], 0.1f * zacc[nt][1]);
                if (e < 128) *(float2*)(sZ2 + g * ND + e) = v;
                else         *(float2*)(sZ3 + g * ND + (e - 128)) = v;
            }
        }
    }
    // (no barrier: sZ consumed after the post-GEMM barrier)

    // ---- main GEMM: [128 x 128] = fp16(u) @ fp16(W1+I)^T ----
    const int warpM = w >> 1, warpE = w & 1;

    float acc[2][8][4];
#pragma unroll
    for (int mt = 0; mt < 2; mt++)
#pragma unroll
        for (int nt = 0; nt < 8; nt++)
#pragma unroll
            for (int r = 0; r < 4; r++) acc[mt][nt][r] = 0.f;

    const char*  Abase = smem + SUH + (warpM * 32 + g) * ROWH + tg * 4;
    const uint4* Bbase = g_W1h + warpE * 1024 + lane;

#pragma unroll
    for (int ks = 0; ks < 8; ks++) {
        uint32_t a[2][4];
#pragma unroll
        for (int mt = 0; mt < 2; mt++) {
            const char* ar = Abase + mt * 16 * ROWH + ks * 32;
            a[mt][0] = *(const uint32_t*)(ar);
            a[mt][1] = *(const uint32_t*)(ar + 8 * ROWH);
            a[mt][2] = *(const uint32_t*)(ar + 16);
            a[mt][3] = *(const uint32_t*)(ar + 8 * ROWH + 16);
        }
#pragma unroll
        for (int ntp = 0; ntp < 4; ntp++) {
            uint4 bb = Bbase[ntp * 256 + ks * 32];
            mma_f16(acc[0][2 * ntp + 0], a[0], bb.x, bb.y);
            mma_f16(acc[1][2 * ntp + 0], a[1], bb.x, bb.y);
            mma_f16(acc[0][2 * ntp + 1], a[0], bb.z, bb.w);
            mma_f16(acc[1][2 * ntp + 1], a[1], bb.z, bb.w);
        }
    }

    __syncthreads();   // sZ2/sZ3 visible

    // ---- epilogue: + b1 + mask*z3 + (c==mycol)*z2 (residual in GEMM) ----
    const int node = warpM;
    const int mycol = __ldg(coloring + nodeBase + node);
    const float* z2p = sZ2 + node * ND;
    const float* z3p = sZ3 + node * ND;

    float mk[2][2];
    bool  hit[2][2];
    int   lrow[2][2];
#pragma unroll
    for (int mt = 0; mt < 2; mt++)
#pragma unroll
        for (int half = 0; half < 2; half++) {
            int c = mt * 16 + half * 8 + g;
            lrow[mt][half] = warpM * 32 + c;
            mk[mt][half]  = __ldg(mask + rowBase + lrow[mt][half]);
            hit[mt][half] = (c == mycol);
        }

#pragma unroll
    for (int nt = 0; nt < 8; nt++) {
        const int e = warpE * 64 + nt * 8 + tg * 2;
        const float2 bv  = *(const float2*)(sB1 + e);
        const float2 z2v = *(const float2*)(z2p + e);
        const float2 z3v = *(const float2*)(z3p + e);
#pragma unroll
        for (int mt = 0; mt < 2; mt++)
#pragma unroll
            for (int half = 0; half < 2; half++) {
                const int r = lrow[mt][half];
                float v0 = acc[mt][nt][half * 2 + 0] + bv.x + mk[mt][half] * z3v.x;
                float v1 = acc[mt][nt][half * 2 + 1] + bv.y + mk[mt][half] * z3v.y;
                if (hit[mt][half]) { v0 += z2v.x; v1 += z2v.y; }
                *(float2*)(out + (long long)(rowBase + r) * ND + e) =
                    make_float2(v0, v1);
            }
    }
}

// ============================================================================
extern "C" void kernel_launch(void* const* d_in, const int* in_sizes, int n_in,
                              void* d_out, int out_size) {
    const float* u    = (const float*)d_in[0];
    const float* mask = (const float*)d_in[1];
    const float* norm = (const float*)d_in[2];
    const int*   col  = (const int*)d_in[3];
    const float* W1   = (const float*)d_in[4];
    const float* b1   = (const float*)d_in[5];
    const float* W2   = (const float*)d_in[6];
    const float* W3   = (const float*)d_in[7];
    float* out = (float*)d_out;

    static bool attr_set = false;
    if (!attr_set) {
        cudaFuncSetAttribute(fused_kernel,
                             cudaFuncAttributeMaxDynamicSharedMemorySize,
                             SMEM_BYTES);
        attr_set = true;
    }

    prep_kernel<<<24, 256>>>(W1, W2, W3);
    fused_kernel<<<NNODES / 4, 256, SMEM_BYTES>>>(u, mask, norm, col, b1, out);

    (void)in_sizes; (void)n_in; (void)out_size;
}

// round 7
// speedup vs baseline: 4.3556x; 1.0662x over previous
#include <cuda_runtime.h>
#include <cuda_fp16.h>
#include <cstdint>

#define NNODES 20000
#define NC 32
#define ND 128
#define ROWH 272        // fp16 smem row pitch in BYTES (136 halfs): conflict-free

// ---- smem byte offsets ----
#define SUH 0                    // fp16 u tile 128 x 272     = 34816
#define SMH 34816                // fp16 mean 4 x 272         = 1088
#define SZ2 35904                // fp32 z2 4 x 128 x 4       = 2048
#define SZ3 37952                // fp32 z3                   = 2048
#define SB1 40000                // fp32 b1                   = 512
#define SMEM_BYTES 40512

// ---- device scratch: fragment-permuted fp16 weights ----
// g_W1h[wE*1024 + ntp*256 + ks*32 + lane]: lane=(g*4+tg)
//   .x = {M[e][kb], M[e][kb+1]}  .y = {M[e][kb+8], M[e][kb+9]}  (M = W1 + I)
//   .z/.w same for e+8;  e = wE*64+ntp*16+g, kb = ks*16+2tg
__device__ uint4 g_W1h[2048];    // 32 KB
// g_W23h[w*512 + ntp*256 + ks*32 + lane]; rows e: [W2 | W3], e = w*32+ntp*16+g
__device__ uint4 g_W23h[4096];   // 64 KB

__device__ __forceinline__ uint32_t pk(float a, float b) {
    __half2 h = __floats2half2_rn(a, b);
    return *(uint32_t*)&h;
}

__device__ __forceinline__ void mma_f16(float* d, const uint32_t* a,
                                        uint32_t b0, uint32_t b1) {
    asm volatile(
        "mma.sync.aligned.m16n8k16.row.col.f32.f16.f16.f32 "
        "{%0,%1,%2,%3}, {%4,%5,%6,%7}, {%8,%9}, {%0,%1,%2,%3};\n"
        : "+f"(d[0]), "+f"(d[1]), "+f"(d[2]), "+f"(d[3])
        : "r"(a[0]), "r"(a[1]), "r"(a[2]), "r"(a[3]), "r"(b0), "r"(b1));
}

// ============================================================================
// prep: fragment-permuted fp16 weight images; W1 gets +I (residual folded)
// ============================================================================
__global__ void prep_kernel(const float* __restrict__ W1,
                            const float* __restrict__ W2,
                            const float* __restrict__ W3) {
    int t0 = blockIdx.x * blockDim.x + threadIdx.x;
    int stride = gridDim.x * blockDim.x;
    for (int i = t0; i < 2048; i += stride) {
        int lane = i & 31, ks = (i >> 5) & 7, ntp = (i >> 8) & 3, wE = i >> 10;
        int g = lane >> 2, tg = lane & 3;
        int e0 = wE * 64 + ntp * 16 + g, e1 = e0 + 8;
        int kb = ks * 16 + 2 * tg;
        uint4 v;
        v.x = pk(W1[e0 * ND + kb]     + (e0 == kb     ? 1.f : 0.f),
                 W1[e0 * ND + kb + 1] + (e0 == kb + 1 ? 1.f : 0.f));
        v.y = pk(W1[e0 * ND + kb + 8] + (e0 == kb + 8 ? 1.f : 0.f),
                 W1[e0 * ND + kb + 9] + (e0 == kb + 9 ? 1.f : 0.f));
        v.z = pk(W1[e1 * ND + kb]     + (e1 == kb     ? 1.f : 0.f),
                 W1[e1 * ND + kb + 1] + (e1 == kb + 1 ? 1.f : 0.f));
        v.w = pk(W1[e1 * ND + kb + 8] + (e1 == kb + 8 ? 1.f : 0.f),
                 W1[e1 * ND + kb + 9] + (e1 == kb + 9 ? 1.f : 0.f));
        g_W1h[i] = v;
    }
    for (int i = t0; i < 4096; i += stride) {
        int lane = i & 31, ks = (i >> 5) & 7, ntp = (i >> 8) & 1, w = i >> 9;
        int g = lane >> 2, tg = lane & 3;
        int e0 = w * 32 + ntp * 16 + g, e1 = e0 + 8;
        int kb = ks * 16 + 2 * tg;
        const float* r0 = (e0 < 128) ? (W2 + e0 * ND) : (W3 + (e0 - 128) * ND);
        const float* r1 = (e1 < 128) ? (W2 + e1 * ND) : (W3 + (e1 - 128) * ND);
        uint4 v;
        v.x = pk(r0[kb], r0[kb + 1]);
        v.y = pk(r0[kb + 8], r0[kb + 9]);
        v.z = pk(r1[kb], r1[kb + 1]);
        v.w = pk(r1[kb + 8], r1[kb + 9]);
        g_W23h[i] = v;
    }
}

// ============================================================================
// Fused kernel: 4 nodes (128 rows) per CTA, 128 threads (4 warps), fat tiles:
// each warp computes a 64x64 output tile -> operand L1 traffic minimized.
// ============================================================================
__global__ void __launch_bounds__(128)
fused_kernel(const float* __restrict__ u,
             const float* __restrict__ mask,
             const float* __restrict__ normalizer,
             const int* __restrict__ coloring,
             const float* __restrict__ b1,
             float* __restrict__ out) {
    extern __shared__ char smem[];
    float* sZ2 = (float*)(smem + SZ2);
    float* sZ3 = (float*)(smem + SZ3);
    float* sB1 = (float*)(smem + SB1);

    const int t = threadIdx.x;
    const int rowBase = blockIdx.x * 128;
    const int nodeBase = blockIdx.x * 4;

    // ---- stage u -> fp16 tile, coalesced float4 loads ----
    {
        const float4* ug = (const float4*)(u + (long long)rowBase * ND);
#pragma unroll
        for (int i = 0; i < 32; i++) {
            int idx = t + i * 128;              // 0..4095
            int row = idx >> 5, c4 = idx & 31;
            float4 v = ug[idx];
            uint2 h;
            h.x = pk(v.x, v.y);
            h.y = pk(v.z, v.w);
            *(uint2*)(smem + SUH + row * ROWH + c4 * 8) = h;
        }
    }
    if (t < 32) *(float4*)(sB1 + t * 4) = ((const float4*)b1)[t];
    __syncthreads();

    const int w = t >> 5, lane = t & 31;
    const int g = lane >> 2, tg = lane & 3;

    // ---- mean over colors from fp16 tile (warp = node) ----
    {
        int node = w;
        float inv = 1.f / normalizer[nodeBase + node];
        const char* base = smem + SUH + (node * 32) * ROWH;
#pragma unroll
        for (int rep = 0; rep < 2; rep++) {
            int dp = lane + rep * 32;          // channel pair 0..63
            const char* p = base + dp * 4;
            float sx = 0.f, sy = 0.f;
#pragma unroll
            for (int c = 0; c < NC; c++) {
                __half2 h = *(const __half2*)(p + c * ROWH);
                float2 f = __half22float2(h);
                sx += f.x; sy += f.y;
            }
            *(uint32_t*)(smem + SMH + node * ROWH + dp * 4) = pk(sx * inv, sy * inv);
        }
    }
    __syncthreads();

    // ---- z2/z3: mean(4x128, M-pad 16) @ [W2;W3]^T via fp16 mma ----
    // 4 warps x 2 reps cover the 256 e-rows of [W2;W3].
    {
        const char* Ab = smem + SMH + g * ROWH + tg * 4;
        const bool valid = (g < 4);
#pragma unroll
        for (int rep = 0; rep < 2; rep++) {
            const int wz = w + rep * 4;        // e-slice 0..7
            float zacc[4][4];
#pragma unroll
            for (int n = 0; n < 4; n++)
#pragma unroll
                for (int r = 0; r < 4; r++) zacc[n][r] = 0.f;

            const uint4* Bp = g_W23h + wz * 512 + lane;
#pragma unroll
            for (int ks = 0; ks < 8; ks++) {
                uint32_t a[4];
                a[0] = valid ? *(const uint32_t*)(Ab + ks * 32) : 0u;
                a[1] = 0u;                      // rows 8..15 padding
                a[2] = valid ? *(const uint32_t*)(Ab + ks * 32 + 16) : 0u;
                a[3] = 0u;
#pragma unroll
                for (int ntp = 0; ntp < 2; ntp++) {
                    uint4 bb = Bp[ntp * 256 + ks * 32];
                    mma_f16(zacc[2 * ntp + 0], a, bb.x, bb.y);
                    mma_f16(zacc[2 * ntp + 1], a, bb.z, bb.w);
                }
            }
            if (valid) {
#pragma unroll
                for (int nt = 0; nt < 4; nt++) {
                    int e = wz * 32 + nt * 8 + tg * 2;
                    float2 v = make_float2(0.1f * zacc[nt][0], 0.1f * zacc[nt][1]);
                    if (e < 128) *(float2*)(sZ2 + g * ND + e) = v;
                    else         *(float2*)(sZ3 + g * ND + (e - 128)) = v;
                }
            }
        }
    }
    // (no barrier: sZ consumed after the post-GEMM barrier)

    // ---- main GEMM: warp tile 64x64: fp16(u) @ fp16(W1+I)^T ----
    const int warpM = w >> 1, warpE = w & 1;

    float acc[4][8][4];
#pragma unroll
    for (int mt = 0; mt < 4; mt++)
#pragma unroll
        for (int nt = 0; nt < 8; nt++)
#pragma unroll
            for (int r = 0; r < 4; r++) acc[mt][nt][r] = 0.f;

    const char*  Abase = smem + SUH + (warpM * 64 + g) * ROWH + tg * 4;
    const uint4* Bbase = g_W1h + warpE * 1024 + lane;

#pragma unroll
    for (int ks = 0; ks < 8; ks++) {
        uint32_t a[4][4];
#pragma unroll
        for (int mt = 0; mt < 4; mt++) {
            const char* ar = Abase + mt * 16 * ROWH + ks * 32;
            a[mt][0] = *(const uint32_t*)(ar);
            a[mt][1] = *(const uint32_t*)(ar + 8 * ROWH);
            a[mt][2] = *(const uint32_t*)(ar + 16);
            a[mt][3] = *(const uint32_t*)(ar + 8 * ROWH + 16);
        }
#pragma unroll
        for (int ntp = 0; ntp < 4; ntp++) {
            uint4 bb = Bbase[ntp * 256 + ks * 32];
#pragma unroll
            for (int mt = 0; mt < 4; mt++) {
                mma_f16(acc[mt][2 * ntp + 0], a[mt], bb.x, bb.y);
                mma_f16(acc[mt][2 * ntp + 1], a[mt], bb.z, bb.w);
            }
        }
    }

    __syncthreads();   // sZ2/sZ3 visible

    // ---- epilogue: + b1 + mask*z3 + (c==mycol)*z2 (residual in GEMM) ----
    // warp covers rows warpM*64 .. +63 = local nodes {warpM*2, warpM*2+1}
    const int nA = warpM * 2, nB = nA + 1;
    const int colA = __ldg(coloring + nodeBase + nA);
    const int colB = __ldg(coloring + nodeBase + nB);

    float mk[4][2];
    bool  hit[4][2];
    int   lrow[4][2];
#pragma unroll
    for (int mt = 0; mt < 4; mt++)
#pragma unroll
        for (int half = 0; half < 2; half++) {
            int r = warpM * 64 + mt * 16 + half * 8 + g;
            int c = r & 31;
            lrow[mt][half] = r;
            mk[mt][half]  = __ldg(mask + rowBase + r);
            hit[mt][half] = (c == ((mt < 2) ? colA : colB));
        }

#pragma unroll
    for (int nt = 0; nt < 8; nt++) {
        const int e = warpE * 64 + nt * 8 + tg * 2;
        const float2 bv   = *(const float2*)(sB1 + e);
        const float2 z2A  = *(const float2*)(sZ2 + nA * ND + e);
        const float2 z3A  = *(const float2*)(sZ3 + nA * ND + e);
        const float2 z2B  = *(const float2*)(sZ2 + nB * ND + e);
        const float2 z3B  = *(const float2*)(sZ3 + nB * ND + e);
#pragma unroll
        for (int mt = 0; mt < 4; mt++) {
            const float2 z2v = (mt < 2) ? z2A : z2B;
            const float2 z3v = (mt < 2) ? z3A : z3B;
#pragma unroll
            for (int half = 0; half < 2; half++) {
                const int r = lrow[mt][half];
                float v0 = acc[mt][nt][half * 2 + 0] + bv.x + mk[mt][half] * z3v.x;
                float v1 = acc[mt][nt][half * 2 + 1] + bv.y + mk[mt][half] * z3v.y;
                if (hit[mt][half]) { v0 += z2v.x; v1 += z2v.y; }
                *(float2*)(out + (long long)(rowBase + r) * ND + e) =
                    make_float2(v0, v1);
            }
        }
    }
}

// ============================================================================
extern "C" void kernel_launch(void* const* d_in, const int* in_sizes, int n_in,
                              void* d_out, int out_size) {
    const float* u    = (const float*)d_in[0];
    const float* mask = (const float*)d_in[1];
    const float* norm = (const float*)d_in[2];
    const int*   col  = (const int*)d_in[3];
    const float* W1   = (const float*)d_in[4];
    const float* b1   = (const float*)d_in[5];
    const float* W2   = (const float*)d_in[6];
    const float* W3   = (const float*)d_in[7];
    float* out = (float*)d_out;

    static bool attr_set = false;
    if (!attr_set) {
        cudaFuncSetAttribute(fused_kernel,
                             cudaFuncAttributeMaxDynamicSharedMemorySize,
                             SMEM_BYTES);
        attr_set = true;
    }

    prep_kernel<<<24, 256>>>(W1, W2, W3);
    fused_kernel<<<NNODES / 4, 128, SMEM_BYTES>>>(u, mask, norm, col, b1, out);

    (void)in_sizes; (void)n_in; (void)out_size;
}